// round 2
// baseline (speedup 1.0000x reference)
#include <cuda_runtime.h>
#include <cuda_bf16.h>

// ContinuousEmbedding: x:[64,8192] f32 in [-1,1), emb:[64,128] f32.
// xs = (x+1)*32; 8-point Hann window (size 8) weights, normalized;
// out[x,:] = sum_j w_j * emb[p_base+j, :]  -> [64,8192,128] f32.
//
// R1 optimization: per-lane weight precompute (trig/mask/normalize hoisted
// out of the broadcast loop) + zero-padded smem table (no per-k clamping).
// Hot loop per x: 9 SHFL + 8 LDS.128 + 32 FFMA + 1 STG.128.

#define NUM_POINTS 64
#define OUT_DIMS   128
#define PAD        4                    // guard rows each side (zeroed)
#define ROWS_PAD   (NUM_POINTS + 2*PAD) // 72
#define V4_PER_ROW (OUT_DIMS / 4)       // 32

__global__ __launch_bounds__(256)
void ContinuousEmbedding_89412629168402_kernel(const float* __restrict__ x,
                                               const float* __restrict__ emb,
                                               float* __restrict__ out,
                                               int n_x)
{
    __shared__ float emb_s[ROWS_PAD * OUT_DIMS];   // 72*128*4 = 36 KB

    // Stage table into rows [PAD, PAD+64); zero the guard rows.
    {
        const float4* emb4 = reinterpret_cast<const float4*>(emb);
        float4* mid = reinterpret_cast<float4*>(emb_s + PAD * OUT_DIMS);
        #pragma unroll
        for (int i = threadIdx.x; i < NUM_POINTS * V4_PER_ROW; i += 256)
            mid[i] = emb4[i];

        float4 z = make_float4(0.f, 0.f, 0.f, 0.f);
        float4* lo = reinterpret_cast<float4*>(emb_s);
        float4* hi = reinterpret_cast<float4*>(emb_s + (PAD + NUM_POINTS) * OUT_DIMS);
        #pragma unroll
        for (int i = threadIdx.x; i < PAD * V4_PER_ROW; i += 256) {
            lo[i] = z;
            hi[i] = z;
        }
    }
    __syncthreads();

    const int warp = blockIdx.x * (blockDim.x >> 5) + (threadIdx.x >> 5);
    const int lane = threadIdx.x & 31;
    const int base = warp * 32;
    if (base >= n_x) return;

    // ---- per-lane precompute: weights for THIS lane's x ----
    float xv = 0.0f;
    if (base + lane < n_x) xv = x[base + lane];

    const float xs = (xv + 1.0f) * 32.0f;
    const float f  = floorf(xs);
    const int   pb = (int)f - 3;          // window rows pb..pb+7
    const float t  = xs - f;

    // w_j = cos^2(pi*(t+3-j)/8) = 0.5 + 0.5*cos(a - j*pi/4), a=(pi/4)(t+3)
    const float R  = 0.70710678118654752440f;
    const float a  = 0.78539816339744830962f * (t + 3.0f);
    const float ca = __cosf(a);
    const float sa = __sinf(a);
    const float hc = 0.5f * ca;
    const float hs = 0.5f * sa;
    const float u  = 0.5f * R * (ca + sa);
    const float v  = 0.5f * R * (sa - ca);

    float w[8];
    w[0] = 0.5f + hc;  w[1] = 0.5f + u;
    w[2] = 0.5f + hs;  w[3] = 0.5f + v;
    w[4] = 0.5f - hc;  w[5] = 0.5f - u;
    w[6] = 0.5f - hs;  w[7] = 0.5f - v;

    float s = 0.0f;
    #pragma unroll
    for (int j = 0; j < 8; ++j) {
        const int p = pb + j;
        if (p < 0 || p >= NUM_POINTS) w[j] = 0.0f;
        s += w[j];
    }
    const float inv = (s > 0.0f) ? (1.0f / s) : 0.0f;
    #pragma unroll
    for (int j = 0; j < 8; ++j) w[j] *= inv;

    // ---- broadcast loop: one x per iteration ----
    float4* __restrict__ out4 = reinterpret_cast<float4*>(out);
    const int cnt = min(32, n_x - base);

    for (int k = 0; k < cnt; ++k) {
        const int pbk = __shfl_sync(0xffffffffu, pb, k);
        float vw[8];
        #pragma unroll
        for (int j = 0; j < 8; ++j)
            vw[j] = __shfl_sync(0xffffffffu, w[j], k);

        const float* row = emb_s + ((pbk + PAD) << 7) + (lane << 2);

        float4 acc = make_float4(0.f, 0.f, 0.f, 0.f);
        #pragma unroll
        for (int j = 0; j < 8; ++j) {
            const float4 e = *reinterpret_cast<const float4*>(row + j * OUT_DIMS);
            acc.x = fmaf(vw[j], e.x, acc.x);
            acc.y = fmaf(vw[j], e.y, acc.y);
            acc.z = fmaf(vw[j], e.z, acc.z);
            acc.w = fmaf(vw[j], e.w, acc.w);
        }

        out4[(size_t)(base + k) * V4_PER_ROW + lane] = acc;
    }
}

extern "C" void kernel_launch(void* const* d_in, const int* in_sizes, int n_in,
                              void* d_out, int out_size)
{
    const float* x   = (const float*)d_in[0];   // [64, 8192] f32
    const float* emb = (const float*)d_in[1];   // [64, 128]  f32
    float* out = (float*)d_out;                 // [64, 8192, 128] f32

    const int n_x = in_sizes[0];                // 524288
    const int warps  = (n_x + 31) / 32;
    const int blocks = (warps + 7) / 8;         // 256 threads = 8 warps/block
    ContinuousEmbedding_89412629168402_kernel<<<blocks, 256>>>(x, emb, out, n_x);
}

// round 3
// speedup vs baseline: 1.6090x; 1.6090x over previous
#include <cuda_runtime.h>
#include <cuda_bf16.h>

// ContinuousEmbedding via trig factorization:
//   w_j = 0.5 + 0.5*cos(a)cos(j*pi/4) + 0.5*sin(a)sin(j*pi/4),  a=(pi/4)(t+3)
//   out[x] = inv * (0.5*A0[pb] + 0.5*ca*A1[pb] + 0.5*sa*A2[pb])
// with A0/A1/A2 precomputed per-block in smem over pb (E zeroed outside grid,
// which reproduces boundary masking exactly). 3 LDS.128 per x instead of 8.

#define NUM_POINTS 64
#define OUT_DIMS   128
#define V4_PER_ROW (OUT_DIMS / 4)        // 32
#define NPBI       65                    // pbi = pb+3 in [0,64]
#define TBL_F4     (NPBI * 3 * V4_PER_ROW)   // 6240 float4 = 99840 B
#define RSQ2       0.70710678118654752440f

extern __shared__ float4 s_tbl[];        // [pbi][3][32] float4

__global__ __launch_bounds__(256)
void ContinuousEmbedding_89412629168402_kernel(const float* __restrict__ x,
                                               const float* __restrict__ emb,
                                               float* __restrict__ out,
                                               int n_x)
{
    // ---- build A0/A1/A2 tables (once per block) ----
    const float4* __restrict__ emb4 = reinterpret_cast<const float4*>(emb);
    {
        const float cj[8] = {1.f,  RSQ2, 0.f, -RSQ2, -1.f, -RSQ2,  0.f,  RSQ2};
        const float sj[8] = {0.f,  RSQ2, 1.f,  RSQ2,  0.f, -RSQ2, -1.f, -RSQ2};
        for (int tr = threadIdx.x; tr < NPBI * V4_PER_ROW; tr += 256) {
            const int pbi = tr >> 5;
            const int ch  = tr & 31;
            const int pb  = pbi - 3;
            float4 a0 = make_float4(0.f,0.f,0.f,0.f);
            float4 a1 = a0, a2 = a0;
            #pragma unroll
            for (int j = 0; j < 8; ++j) {
                const int p = pb + j;
                if (p >= 0 && p < NUM_POINTS) {
                    const float4 e = __ldg(&emb4[p * V4_PER_ROW + ch]);
                    a0.x += e.x; a0.y += e.y; a0.z += e.z; a0.w += e.w;
                    a1.x = fmaf(cj[j], e.x, a1.x); a1.y = fmaf(cj[j], e.y, a1.y);
                    a1.z = fmaf(cj[j], e.z, a1.z); a1.w = fmaf(cj[j], e.w, a1.w);
                    a2.x = fmaf(sj[j], e.x, a2.x); a2.y = fmaf(sj[j], e.y, a2.y);
                    a2.z = fmaf(sj[j], e.z, a2.z); a2.w = fmaf(sj[j], e.w, a2.w);
                }
            }
            float4* row = s_tbl + pbi * (3 * V4_PER_ROW) + ch;
            row[0]              = a0;
            row[V4_PER_ROW]     = a1;
            row[2 * V4_PER_ROW] = a2;
        }
    }
    __syncthreads();

    const int lane     = threadIdx.x & 31;
    const int wid_g    = blockIdx.x * (blockDim.x >> 5) + (threadIdx.x >> 5);
    const int w_total  = gridDim.x * (blockDim.x >> 5);
    const int n_tiles  = (n_x + 31) >> 5;

    float4* __restrict__ out4 = reinterpret_cast<float4*>(out);

    const float cj[8] = {1.f,  RSQ2, 0.f, -RSQ2, -1.f, -RSQ2,  0.f,  RSQ2};
    const float sj[8] = {0.f,  RSQ2, 1.f,  RSQ2,  0.f, -RSQ2, -1.f, -RSQ2};

    for (int wt = wid_g; wt < n_tiles; wt += w_total) {
        const int base = wt << 5;

        // ---- per-lane precompute for this lane's x ----
        const int xi = base + lane;
        const float xv = (xi < n_x) ? x[xi] : 0.f;
        const float xs = (xv + 1.0f) * 32.0f;
        const float f  = floorf(xs);
        const int   pb = (int)f - 3;
        const float t  = xs - f;
        const float a  = 0.78539816339744830962f * (t + 3.0f);
        const float ca = __cosf(a);
        const float sa = __sinf(a);

        float n0 = 0.f, n1 = 0.f, n2 = 0.f;
        #pragma unroll
        for (int j = 0; j < 8; ++j) {
            const int p = pb + j;
            if (p >= 0 && p < NUM_POINTS) { n0 += 1.f; n1 += cj[j]; n2 += sj[j]; }
        }
        const float s   = 0.5f * (n0 + ca * n1 + sa * n2);
        const float inv = (s > 0.f) ? (1.0f / s) : 0.f;
        const float c0  = 0.5f * inv;
        const float c1  = 0.5f * ca * inv;
        const float c2  = 0.5f * sa * inv;
        int pbi = pb + 3;
        pbi = max(0, min(NPBI - 1, pbi));

        // ---- broadcast loop: one x per k ----
        const int cnt = min(32, n_x - base);
        for (int k = 0; k < cnt; ++k) {
            const int   pk = __shfl_sync(0xffffffffu, pbi, k);
            const float b0 = __shfl_sync(0xffffffffu, c0, k);
            const float b1 = __shfl_sync(0xffffffffu, c1, k);
            const float b2 = __shfl_sync(0xffffffffu, c2, k);

            const float4* row = s_tbl + pk * (3 * V4_PER_ROW) + lane;
            const float4 A0 = row[0];
            const float4 A1 = row[V4_PER_ROW];
            const float4 A2 = row[2 * V4_PER_ROW];

            float4 acc;
            acc.x = fmaf(b2, A2.x, fmaf(b1, A1.x, b0 * A0.x));
            acc.y = fmaf(b2, A2.y, fmaf(b1, A1.y, b0 * A0.y));
            acc.z = fmaf(b2, A2.z, fmaf(b1, A1.z, b0 * A0.z));
            acc.w = fmaf(b2, A2.w, fmaf(b1, A1.w, b0 * A0.w));

            out4[(size_t)(base + k) * V4_PER_ROW + lane] = acc;
        }
    }
}

extern "C" void kernel_launch(void* const* d_in, const int* in_sizes, int n_in,
                              void* d_out, int out_size)
{
    const float* x   = (const float*)d_in[0];   // [64, 8192] f32
    const float* emb = (const float*)d_in[1];   // [64, 128]  f32
    float* out = (float*)d_out;                 // [64, 8192, 128] f32

    const int n_x = in_sizes[0];                // 524288
    const int smem_bytes = TBL_F4 * (int)sizeof(float4);   // 99840

    static bool attr_set = false;
    if (!attr_set) {
        cudaFuncSetAttribute(ContinuousEmbedding_89412629168402_kernel,
                             cudaFuncAttributeMaxDynamicSharedMemorySize,
                             smem_bytes);
        attr_set = true;
    }

    // persistent-ish grid: 2 CTAs/SM on 148-152 SMs, grid-stride over tiles
    const int blocks = 304;
    ContinuousEmbedding_89412629168402_kernel<<<blocks, 256, smem_bytes>>>(
        x, emb, out, n_x);
}

// round 4
// speedup vs baseline: 1.8758x; 1.1658x over previous
#include <cuda_runtime.h>
#include <cuda_bf16.h>

// ContinuousEmbedding via trig factorization:
//   w_j = 0.5 + 0.5*cos(a)cos(j*pi/4) + 0.5*sin(a)sin(j*pi/4),  a=(pi/4)(t+3)
//   out[x] = inv * (0.5*A0[pb] + 0.5*ca*A1[pb] + 0.5*sa*A2[pb])
// A0/A1/A2 precomputed per-block in smem over pb (E zeroed outside the grid,
// reproducing boundary masking exactly). 3 LDS.128 per x.
//
// R3: 512-thread blocks -> table smem cost amortized over 16 warps;
// 2 CTAs/SM = 32 warps/SM (occ 24% -> ~50%) to saturate the L1 crossbar.

#define NUM_POINTS 64
#define OUT_DIMS   128
#define V4_PER_ROW (OUT_DIMS / 4)        // 32
#define NPBI       65                    // pbi = pb+3 in [0,64]
#define TBL_F4     (NPBI * 3 * V4_PER_ROW)   // 6240 float4 = 99840 B
#define RSQ2       0.70710678118654752440f
#define BLOCK      512

extern __shared__ float4 s_tbl[];        // [pbi][3][32] float4

__global__ __launch_bounds__(BLOCK)
void ContinuousEmbedding_89412629168402_kernel(const float* __restrict__ x,
                                               const float* __restrict__ emb,
                                               float* __restrict__ out,
                                               int n_x)
{
    // ---- build A0/A1/A2 tables (once per block) ----
    const float4* __restrict__ emb4 = reinterpret_cast<const float4*>(emb);
    {
        const float cj[8] = {1.f,  RSQ2, 0.f, -RSQ2, -1.f, -RSQ2,  0.f,  RSQ2};
        const float sj[8] = {0.f,  RSQ2, 1.f,  RSQ2,  0.f, -RSQ2, -1.f, -RSQ2};
        for (int tr = threadIdx.x; tr < NPBI * V4_PER_ROW; tr += BLOCK) {
            const int pbi = tr >> 5;
            const int ch  = tr & 31;
            const int pb  = pbi - 3;
            float4 a0 = make_float4(0.f,0.f,0.f,0.f);
            float4 a1 = a0, a2 = a0;
            #pragma unroll
            for (int j = 0; j < 8; ++j) {
                const int p = pb + j;
                if (p >= 0 && p < NUM_POINTS) {
                    const float4 e = __ldg(&emb4[p * V4_PER_ROW + ch]);
                    a0.x += e.x; a0.y += e.y; a0.z += e.z; a0.w += e.w;
                    a1.x = fmaf(cj[j], e.x, a1.x); a1.y = fmaf(cj[j], e.y, a1.y);
                    a1.z = fmaf(cj[j], e.z, a1.z); a1.w = fmaf(cj[j], e.w, a1.w);
                    a2.x = fmaf(sj[j], e.x, a2.x); a2.y = fmaf(sj[j], e.y, a2.y);
                    a2.z = fmaf(sj[j], e.z, a2.z); a2.w = fmaf(sj[j], e.w, a2.w);
                }
            }
            float4* row = s_tbl + pbi * (3 * V4_PER_ROW) + ch;
            row[0]              = a0;
            row[V4_PER_ROW]     = a1;
            row[2 * V4_PER_ROW] = a2;
        }
    }
    __syncthreads();

    const int lane     = threadIdx.x & 31;
    const int wid_g    = blockIdx.x * (BLOCK >> 5) + (threadIdx.x >> 5);
    const int w_total  = gridDim.x * (BLOCK >> 5);
    const int n_tiles  = (n_x + 31) >> 5;

    float4* __restrict__ out4 = reinterpret_cast<float4*>(out);

    const float cj[8] = {1.f,  RSQ2, 0.f, -RSQ2, -1.f, -RSQ2,  0.f,  RSQ2};
    const float sj[8] = {0.f,  RSQ2, 1.f,  RSQ2,  0.f, -RSQ2, -1.f, -RSQ2};

    for (int wt = wid_g; wt < n_tiles; wt += w_total) {
        const int base = wt << 5;

        // ---- per-lane precompute for this lane's x ----
        const int xi = base + lane;
        const float xv = (xi < n_x) ? x[xi] : 0.f;
        const float xs = (xv + 1.0f) * 32.0f;
        const float f  = floorf(xs);
        const int   pb = (int)f - 3;
        const float t  = xs - f;
        const float a  = 0.78539816339744830962f * (t + 3.0f);
        const float ca = __cosf(a);
        const float sa = __sinf(a);

        float n0 = 0.f, n1 = 0.f, n2 = 0.f;
        #pragma unroll
        for (int j = 0; j < 8; ++j) {
            const int p = pb + j;
            if (p >= 0 && p < NUM_POINTS) { n0 += 1.f; n1 += cj[j]; n2 += sj[j]; }
        }
        const float s   = 0.5f * (n0 + ca * n1 + sa * n2);
        const float inv = (s > 0.f) ? (1.0f / s) : 0.f;
        const float c0  = 0.5f * inv;
        const float c1  = 0.5f * ca * inv;
        const float c2  = 0.5f * sa * inv;
        int pbi = pb + 3;
        pbi = max(0, min(NPBI - 1, pbi));

        // ---- broadcast loop: one x per k ----
        const int cnt = min(32, n_x - base);
        for (int k = 0; k < cnt; ++k) {
            const int   pk = __shfl_sync(0xffffffffu, pbi, k);
            const float b0 = __shfl_sync(0xffffffffu, c0, k);
            const float b1 = __shfl_sync(0xffffffffu, c1, k);
            const float b2 = __shfl_sync(0xffffffffu, c2, k);

            const float4* row = s_tbl + pk * (3 * V4_PER_ROW) + lane;
            const float4 A0 = row[0];
            const float4 A1 = row[V4_PER_ROW];
            const float4 A2 = row[2 * V4_PER_ROW];

            float4 acc;
            acc.x = fmaf(b2, A2.x, fmaf(b1, A1.x, b0 * A0.x));
            acc.y = fmaf(b2, A2.y, fmaf(b1, A1.y, b0 * A0.y));
            acc.z = fmaf(b2, A2.z, fmaf(b1, A1.z, b0 * A0.z));
            acc.w = fmaf(b2, A2.w, fmaf(b1, A1.w, b0 * A0.w));

            // streaming store: output is write-once, keep it out of L2 residency
            __stcs(&out4[(size_t)(base + k) * V4_PER_ROW + lane], acc);
        }
    }
}

extern "C" void kernel_launch(void* const* d_in, const int* in_sizes, int n_in,
                              void* d_out, int out_size)
{
    const float* x   = (const float*)d_in[0];   // [64, 8192] f32
    const float* emb = (const float*)d_in[1];   // [64, 128]  f32
    float* out = (float*)d_out;                 // [64, 8192, 128] f32

    const int n_x = in_sizes[0];                // 524288
    const int smem_bytes = TBL_F4 * (int)sizeof(float4);   // 99840

    static bool attr_set = false;
    if (!attr_set) {
        cudaFuncSetAttribute(ContinuousEmbedding_89412629168402_kernel,
                             cudaFuncAttributeMaxDynamicSharedMemorySize,
                             smem_bytes);
        attr_set = true;
    }

    // 2 CTAs/SM * ~152 SMs, grid-stride over 32-x tiles
    const int blocks = 304;
    ContinuousEmbedding_89412629168402_kernel<<<blocks, BLOCK, smem_bytes>>>(
        x, emb, out, n_x);
}